// round 1
// baseline (speedup 1.0000x reference)
#include <cuda_runtime.h>
#include <cstddef>

// ---------------------------------------------------------------------------
// GCN: out = GCNconv3( relu(GCNconv2( relu(GCNconv1(x)) )) )
// GCNconv(x,W,b) = segsum_dst( (x@W)[src] * w_edge ) + b
// w_edge = rsqrt(deg[src]) * rsqrt(deg[dst]),  deg = in-degree over dst
// ---------------------------------------------------------------------------

#define MAX_NODES 100000
#define MAX_EDGES 1600000

// scratch (allocation-free rules: __device__ globals)
__device__ float g_h  [(size_t)MAX_NODES * 128]; // GEMM output / scatter source
__device__ float g_agg[(size_t)MAX_NODES * 128]; // aggregation target / next GEMM input
__device__ float g_deg[MAX_NODES];
__device__ float g_w  [MAX_EDGES];

// ---------------------------------------------------------------------------
__global__ void k_zero_deg(float* deg, int n) {
    int i = blockIdx.x * blockDim.x + threadIdx.x;
    if (i < n) deg[i] = 0.0f;
}

__global__ void k_deg_acc(float* deg, const int* __restrict__ dst, int E) {
    int e = blockIdx.x * blockDim.x + threadIdx.x;
    if (e < E) atomicAdd(&deg[dst[e]], 1.0f);
}

__global__ void k_edge_w(float* __restrict__ w, const float* __restrict__ deg,
                         const int* __restrict__ src, const int* __restrict__ dst, int E) {
    int e = blockIdx.x * blockDim.x + threadIdx.x;
    if (e < E) {
        float a = __ldg(deg + src[e]);
        float b = __ldg(deg + dst[e]);
        float ra = (a > 0.0f) ? rsqrtf(a) : 0.0f;
        float rb = (b > 0.0f) ? rsqrtf(b) : 0.0f;
        w[e] = ra * rb;
    }
}

// out[i*C + j] = b[j]; mask = C-1 (C power of two)
__global__ void k_init_bias(float* __restrict__ o, const float* __restrict__ b,
                            int total, int mask) {
    int i = blockIdx.x * blockDim.x + threadIdx.x;
    if (i < total) o[i] = __ldg(b + (i & mask));
}

// ---------------------------------------------------------------------------
// SGEMM: C[M,N] = A[M,128] @ W[128,N], optional relu on A load.
// Block tile 64x64, BK=16, 256 threads, 4x4 per-thread micro tile.
// ---------------------------------------------------------------------------
__global__ void __launch_bounds__(256)
k_gemm_k128(const float* __restrict__ A, const float* __restrict__ W,
            float* __restrict__ C, int M, int N, int relu_in) {
    __shared__ float As[16][68];   // [k][m], padded
    __shared__ float Ws[16][64];   // [k][n]

    const int tid  = threadIdx.x;
    const int brow = blockIdx.x * 64;
    const int bcol = blockIdx.y * 64;
    const int tx = tid & 15;   // col group (4 cols)
    const int ty = tid >> 4;   // row group (4 rows)

    float acc[4][4];
#pragma unroll
    for (int i = 0; i < 4; i++)
#pragma unroll
        for (int j = 0; j < 4; j++) acc[i][j] = 0.0f;

    // A-load mapping: each thread loads one float4
    const int ar = tid >> 2;         // row within tile  0..63
    const int ak = (tid & 3) * 4;    // k offset         0,4,8,12
    // W-load mapping
    const int wk = tid >> 4;         // k within tile    0..15
    const int wc = (tid & 15) * 4;   // col offset       0..60

    const int arow = brow + ar;

    for (int k0 = 0; k0 < 128; k0 += 16) {
        float4 av = make_float4(0.f, 0.f, 0.f, 0.f);
        if (arow < M)
            av = *(const float4*)(A + (size_t)arow * 128 + k0 + ak);
        if (relu_in) {
            av.x = fmaxf(av.x, 0.f); av.y = fmaxf(av.y, 0.f);
            av.z = fmaxf(av.z, 0.f); av.w = fmaxf(av.w, 0.f);
        }
        As[ak + 0][ar] = av.x;
        As[ak + 1][ar] = av.y;
        As[ak + 2][ar] = av.z;
        As[ak + 3][ar] = av.w;

        float4 wv = *(const float4*)(W + (size_t)(k0 + wk) * N + bcol + wc);
        *(float4*)&Ws[wk][wc] = wv;

        __syncthreads();
#pragma unroll
        for (int kk = 0; kk < 16; kk++) {
            float4 a = *(const float4*)&As[kk][ty * 4];
            float4 b = *(const float4*)&Ws[kk][tx * 4];
            acc[0][0] += a.x * b.x; acc[0][1] += a.x * b.y; acc[0][2] += a.x * b.z; acc[0][3] += a.x * b.w;
            acc[1][0] += a.y * b.x; acc[1][1] += a.y * b.y; acc[1][2] += a.y * b.z; acc[1][3] += a.y * b.w;
            acc[2][0] += a.z * b.x; acc[2][1] += a.z * b.y; acc[2][2] += a.z * b.z; acc[2][3] += a.z * b.w;
            acc[3][0] += a.w * b.x; acc[3][1] += a.w * b.y; acc[3][2] += a.w * b.z; acc[3][3] += a.w * b.w;
        }
        __syncthreads();
    }

#pragma unroll
    for (int i = 0; i < 4; i++) {
        int row = brow + ty * 4 + i;
        if (row < M) {
            float4 o = make_float4(acc[i][0], acc[i][1], acc[i][2], acc[i][3]);
            *(float4*)(C + (size_t)row * N + bcol + tx * 4) = o;
        }
    }
}

// ---------------------------------------------------------------------------
// Scatter-add: agg[dst] += h[src] * w, one warp per edge (C=128).
// Each lane handles one float4; red.global.add.v4.f32 (sm_90+), no return.
// ---------------------------------------------------------------------------
__global__ void k_scatter128(const float* __restrict__ h,
                             const int* __restrict__ src, const int* __restrict__ dst,
                             const float* __restrict__ w, float* agg, int E) {
    int gt = blockIdx.x * blockDim.x + threadIdx.x;
    int e = gt >> 5;
    int lane = gt & 31;
    if (e >= E) return;
    int s = __ldg(src + e);
    int d = __ldg(dst + e);
    float wt = __ldg(w + e);
    float4 v = __ldg((const float4*)(h + (size_t)s * 128) + lane);
    float* out = agg + (size_t)d * 128 + lane * 4;
    asm volatile("red.global.add.v4.f32 [%0], {%1, %2, %3, %4};"
                 :: "l"(out), "f"(v.x * wt), "f"(v.y * wt), "f"(v.z * wt), "f"(v.w * wt)
                 : "memory");
}

// C=64: half-warp per edge
__global__ void k_scatter64(const float* __restrict__ h,
                            const int* __restrict__ src, const int* __restrict__ dst,
                            const float* __restrict__ w, float* agg, int E) {
    int gt = blockIdx.x * blockDim.x + threadIdx.x;
    int e = gt >> 4;
    int l = gt & 15;
    if (e >= E) return;
    int s = __ldg(src + e);
    int d = __ldg(dst + e);
    float wt = __ldg(w + e);
    float4 v = __ldg((const float4*)(h + (size_t)s * 64) + l);
    float* out = agg + (size_t)d * 64 + l * 4;
    asm volatile("red.global.add.v4.f32 [%0], {%1, %2, %3, %4};"
                 :: "l"(out), "f"(v.x * wt), "f"(v.y * wt), "f"(v.z * wt), "f"(v.w * wt)
                 : "memory");
}

// ---------------------------------------------------------------------------
extern "C" void kernel_launch(void* const* d_in, const int* in_sizes, int n_in,
                              void* d_out, int out_size) {
    const float* x  = (const float*)d_in[0];
    const int*   ei = (const int*)  d_in[1];
    const float* W1 = (const float*)d_in[2];
    const float* b1 = (const float*)d_in[3];
    const float* W2 = (const float*)d_in[4];
    const float* b2 = (const float*)d_in[5];
    const float* W3 = (const float*)d_in[6];
    const float* b3 = (const float*)d_in[7];

    const int E = in_sizes[1] / 2;      // edge_index is [2, E]
    const int M = in_sizes[0] / 128;    // nodes
    const int* src = ei;
    const int* dst = ei + E;

    float *h, *agg, *deg, *w;
    cudaGetSymbolAddress((void**)&h,   g_h);
    cudaGetSymbolAddress((void**)&agg, g_agg);
    cudaGetSymbolAddress((void**)&deg, g_deg);
    cudaGetSymbolAddress((void**)&w,   g_w);
    float* out = (float*)d_out;

    // --- edge normalization weights ---
    k_zero_deg<<<(M + 255) / 256, 256>>>(deg, M);
    k_deg_acc <<<(E + 255) / 256, 256>>>(deg, dst, E);
    k_edge_w  <<<(E + 255) / 256, 256>>>(w, deg, src, dst, E);

    dim3 gemm_grid2((M + 63) / 64, 2);  // N=128
    dim3 gemm_grid1((M + 63) / 64, 1);  // N=64

    // --- layer 1: h = x@W1; agg = segsum + b1 (relu folded into next GEMM) ---
    k_gemm_k128<<<gemm_grid2, 256>>>(x, W1, h, M, 128, 0);
    k_init_bias<<<(M * 128 + 255) / 256, 256>>>(agg, b1, M * 128, 127);
    k_scatter128<<<(E + 7) / 8, 256>>>(h, src, dst, w, agg, E);

    // --- layer 2 ---
    k_gemm_k128<<<gemm_grid2, 256>>>(agg, W2, h, M, 128, 1);
    k_init_bias<<<(M * 128 + 255) / 256, 256>>>(agg, b2, M * 128, 127);
    k_scatter128<<<(E + 7) / 8, 256>>>(h, src, dst, w, agg, E);

    // --- layer 3 (N=64, no relu on output) ---
    k_gemm_k128<<<gemm_grid1, 256>>>(agg, W3, h, M, 64, 1);
    k_init_bias<<<(M * 64 + 255) / 256, 256>>>(out, b3, M * 64, 63);
    k_scatter64<<<((E + 1) / 2 * 32 + 255) / 256, 256>>>(h, src, dst, w, out, E);
}

// round 2
// speedup vs baseline: 1.9808x; 1.9808x over previous
#include <cuda_runtime.h>
#include <cstddef>

// ---------------------------------------------------------------------------
// GCN, CSR-gather formulation (no float atomics):
//   w[e] = dinv[src]*dinv[dst]  factorizes, so
//   layer(X) = diag(dinv) * A_csr_sum( diag(dinv) * (relu(X) @ W) ) + b
// dinv folded into GEMM epilogue; dinv[dst]+bias folded into gather epilogue.
// ---------------------------------------------------------------------------

#define MAX_NODES 100000
#define MAX_EDGES 1600000
#define SCAN_BLK  1024

__device__ float g_h  [(size_t)MAX_NODES * 128];
__device__ float g_agg[(size_t)MAX_NODES * 128];
__device__ int   g_deg [MAX_NODES];
__device__ float g_dinv[MAX_NODES];
__device__ int   g_off [MAX_NODES + 1];
__device__ int   g_cur [MAX_NODES];
__device__ int   g_csr [MAX_EDGES];
__device__ int   g_bsum[(MAX_NODES + SCAN_BLK - 1) / SCAN_BLK];

// ---------------------------------------------------------------------------
__global__ void k_zero_deg(int* deg, int n) {
    int i = blockIdx.x * blockDim.x + threadIdx.x;
    if (i < n) deg[i] = 0;
}

__global__ void k_count(int* deg, const int* __restrict__ dst, int E) {
    int e = blockIdx.x * blockDim.x + threadIdx.x;
    if (e < E) atomicAdd(&deg[dst[e]], 1);
}

__global__ void k_dinv(float* __restrict__ dinv, const int* __restrict__ deg, int n) {
    int i = blockIdx.x * blockDim.x + threadIdx.x;
    if (i < n) {
        int d = deg[i];
        dinv[i] = (d > 0) ? rsqrtf((float)d) : 0.0f;
    }
}

// --- exclusive scan of deg -> off (3 kernels) ---
__global__ void __launch_bounds__(SCAN_BLK)
k_scan1(const int* __restrict__ deg, int* __restrict__ off, int* __restrict__ bsum, int n) {
    __shared__ int sh[SCAN_BLK];
    int i = blockIdx.x * SCAN_BLK + threadIdx.x;
    int x = (i < n) ? deg[i] : 0;
    sh[threadIdx.x] = x;
    __syncthreads();
    // Hillis-Steele inclusive
#pragma unroll
    for (int s = 1; s < SCAN_BLK; s <<= 1) {
        int v = (threadIdx.x >= s) ? sh[threadIdx.x - s] : 0;
        __syncthreads();
        sh[threadIdx.x] += v;
        __syncthreads();
    }
    if (i < n) off[i] = sh[threadIdx.x] - x;          // exclusive
    if (threadIdx.x == SCAN_BLK - 1) bsum[blockIdx.x] = sh[threadIdx.x];
}

__global__ void k_scan2(int* bsum, int nb) {
    if (threadIdx.x == 0) {
        int run = 0;
        for (int b = 0; b < nb; b++) {
            int v = bsum[b];
            bsum[b] = run;
            run += v;
        }
    }
}

__global__ void k_scan3(int* __restrict__ off, int* __restrict__ cur,
                        const int* __restrict__ bsum, int n, int E) {
    int i = blockIdx.x * blockDim.x + threadIdx.x;
    if (i < n) {
        int v = off[i] + bsum[i / SCAN_BLK];
        off[i] = v;
        cur[i] = v;
    }
    if (i == 0) off[n] = E;
}

__global__ void k_place(const int* __restrict__ src, const int* __restrict__ dst,
                        int* cur, int* __restrict__ csr, int E) {
    int e = blockIdx.x * blockDim.x + threadIdx.x;
    if (e < E) {
        int slot = atomicAdd(&cur[dst[e]], 1);
        csr[slot] = src[e];
    }
}

// ---------------------------------------------------------------------------
// SGEMM: C[M,N] = (relu?)A[M,128] @ W[128,N], row-scaled by dinv[row].
// ---------------------------------------------------------------------------
__global__ void __launch_bounds__(256)
k_gemm_k128(const float* __restrict__ A, const float* __restrict__ W,
            float* __restrict__ C, const float* __restrict__ rowscale,
            int M, int N, int relu_in) {
    __shared__ float As[16][68];
    __shared__ float Ws[16][64];

    const int tid  = threadIdx.x;
    const int brow = blockIdx.x * 64;
    const int bcol = blockIdx.y * 64;
    const int tx = tid & 15;
    const int ty = tid >> 4;

    float acc[4][4];
#pragma unroll
    for (int i = 0; i < 4; i++)
#pragma unroll
        for (int j = 0; j < 4; j++) acc[i][j] = 0.0f;

    const int ar = tid >> 2;
    const int ak = (tid & 3) * 4;
    const int wk = tid >> 4;
    const int wc = (tid & 15) * 4;
    const int arow = brow + ar;

    for (int k0 = 0; k0 < 128; k0 += 16) {
        float4 av = make_float4(0.f, 0.f, 0.f, 0.f);
        if (arow < M)
            av = *(const float4*)(A + (size_t)arow * 128 + k0 + ak);
        if (relu_in) {
            av.x = fmaxf(av.x, 0.f); av.y = fmaxf(av.y, 0.f);
            av.z = fmaxf(av.z, 0.f); av.w = fmaxf(av.w, 0.f);
        }
        As[ak + 0][ar] = av.x;
        As[ak + 1][ar] = av.y;
        As[ak + 2][ar] = av.z;
        As[ak + 3][ar] = av.w;

        float4 wv = *(const float4*)(W + (size_t)(k0 + wk) * N + bcol + wc);
        *(float4*)&Ws[wk][wc] = wv;

        __syncthreads();
#pragma unroll
        for (int kk = 0; kk < 16; kk++) {
            float4 a = *(const float4*)&As[kk][ty * 4];
            float4 b = *(const float4*)&Ws[kk][tx * 4];
            acc[0][0] += a.x * b.x; acc[0][1] += a.x * b.y; acc[0][2] += a.x * b.z; acc[0][3] += a.x * b.w;
            acc[1][0] += a.y * b.x; acc[1][1] += a.y * b.y; acc[1][2] += a.y * b.z; acc[1][3] += a.y * b.w;
            acc[2][0] += a.z * b.x; acc[2][1] += a.z * b.y; acc[2][2] += a.z * b.z; acc[2][3] += a.z * b.w;
            acc[3][0] += a.w * b.x; acc[3][1] += a.w * b.y; acc[3][2] += a.w * b.z; acc[3][3] += a.w * b.w;
        }
        __syncthreads();
    }

#pragma unroll
    for (int i = 0; i < 4; i++) {
        int row = brow + ty * 4 + i;
        if (row < M) {
            float sc = __ldg(rowscale + row);
            float4 o = make_float4(acc[i][0] * sc, acc[i][1] * sc,
                                   acc[i][2] * sc, acc[i][3] * sc);
            *(float4*)(C + (size_t)row * N + bcol + tx * 4) = o;
        }
    }
}

// ---------------------------------------------------------------------------
// CSR gather-sum: out[d] = dinv[d] * sum_{e in row d} h[csr[e]] + bias
// C=128: one warp per dst node, lane handles one float4. 4x unroll for MLP.
// ---------------------------------------------------------------------------
__global__ void __launch_bounds__(256)
k_agg128(const float* __restrict__ h, const int* __restrict__ off,
         const int* __restrict__ csr, const float* __restrict__ dinv,
         const float* __restrict__ bias, float* __restrict__ out, int Nn) {
    int gt = blockIdx.x * blockDim.x + threadIdx.x;
    int node = gt >> 5;
    int lane = gt & 31;
    if (node >= Nn) return;
    int i  = __ldg(off + node);
    int s1 = __ldg(off + node + 1);

    float4 acc = make_float4(0.f, 0.f, 0.f, 0.f);
    for (; i + 4 <= s1; i += 4) {
        int sa = __ldg(csr + i);
        int sb = __ldg(csr + i + 1);
        int sc = __ldg(csr + i + 2);
        int sd = __ldg(csr + i + 3);
        float4 va = __ldg((const float4*)(h + (size_t)sa * 128) + lane);
        float4 vb = __ldg((const float4*)(h + (size_t)sb * 128) + lane);
        float4 vc = __ldg((const float4*)(h + (size_t)sc * 128) + lane);
        float4 vd = __ldg((const float4*)(h + (size_t)sd * 128) + lane);
        acc.x += (va.x + vb.x) + (vc.x + vd.x);
        acc.y += (va.y + vb.y) + (vc.y + vd.y);
        acc.z += (va.z + vb.z) + (vc.z + vd.z);
        acc.w += (va.w + vb.w) + (vc.w + vd.w);
    }
    for (; i < s1; i++) {
        int s = __ldg(csr + i);
        float4 v = __ldg((const float4*)(h + (size_t)s * 128) + lane);
        acc.x += v.x; acc.y += v.y; acc.z += v.z; acc.w += v.w;
    }
    float dv = __ldg(dinv + node);
    float4 bv = __ldg((const float4*)bias + lane);
    float4 o = make_float4(acc.x * dv + bv.x, acc.y * dv + bv.y,
                           acc.z * dv + bv.z, acc.w * dv + bv.w);
    *(float4*)(out + (size_t)node * 128 + lane * 4) = o;
}

// C=64: 16 lanes per node (2 nodes per warp)
__global__ void __launch_bounds__(256)
k_agg64(const float* __restrict__ h, const int* __restrict__ off,
        const int* __restrict__ csr, const float* __restrict__ dinv,
        const float* __restrict__ bias, float* __restrict__ out, int Nn) {
    int gt = blockIdx.x * blockDim.x + threadIdx.x;
    int node = gt >> 4;
    int lane = gt & 15;
    if (node >= Nn) return;
    int i  = __ldg(off + node);
    int s1 = __ldg(off + node + 1);

    float4 acc = make_float4(0.f, 0.f, 0.f, 0.f);
    for (; i + 4 <= s1; i += 4) {
        int sa = __ldg(csr + i);
        int sb = __ldg(csr + i + 1);
        int sc = __ldg(csr + i + 2);
        int sd = __ldg(csr + i + 3);
        float4 va = __ldg((const float4*)(h + (size_t)sa * 64) + lane);
        float4 vb = __ldg((const float4*)(h + (size_t)sb * 64) + lane);
        float4 vc = __ldg((const float4*)(h + (size_t)sc * 64) + lane);
        float4 vd = __ldg((const float4*)(h + (size_t)sd * 64) + lane);
        acc.x += (va.x + vb.x) + (vc.x + vd.x);
        acc.y += (va.y + vb.y) + (vc.y + vd.y);
        acc.z += (va.z + vb.z) + (vc.z + vd.z);
        acc.w += (va.w + vb.w) + (vc.w + vd.w);
    }
    for (; i < s1; i++) {
        int s = __ldg(csr + i);
        float4 v = __ldg((const float4*)(h + (size_t)s * 64) + lane);
        acc.x += v.x; acc.y += v.y; acc.z += v.z; acc.w += v.w;
    }
    float dv = __ldg(dinv + node);
    float4 bv = __ldg((const float4*)bias + lane);
    float4 o = make_float4(acc.x * dv + bv.x, acc.y * dv + bv.y,
                           acc.z * dv + bv.z, acc.w * dv + bv.w);
    *(float4*)(out + (size_t)node * 64 + lane * 4) = o;
}

// ---------------------------------------------------------------------------
extern "C" void kernel_launch(void* const* d_in, const int* in_sizes, int n_in,
                              void* d_out, int out_size) {
    const float* x  = (const float*)d_in[0];
    const int*   ei = (const int*)  d_in[1];
    const float* W1 = (const float*)d_in[2];
    const float* b1 = (const float*)d_in[3];
    const float* W2 = (const float*)d_in[4];
    const float* b2 = (const float*)d_in[5];
    const float* W3 = (const float*)d_in[6];
    const float* b3 = (const float*)d_in[7];

    const int E = in_sizes[1] / 2;
    const int M = in_sizes[0] / 128;
    const int* src = ei;
    const int* dst = ei + E;

    float *h, *agg, *dinv;
    int *deg, *off, *cur, *csr, *bsum;
    cudaGetSymbolAddress((void**)&h,    g_h);
    cudaGetSymbolAddress((void**)&agg,  g_agg);
    cudaGetSymbolAddress((void**)&deg,  g_deg);
    cudaGetSymbolAddress((void**)&dinv, g_dinv);
    cudaGetSymbolAddress((void**)&off,  g_off);
    cudaGetSymbolAddress((void**)&cur,  g_cur);
    cudaGetSymbolAddress((void**)&csr,  g_csr);
    cudaGetSymbolAddress((void**)&bsum, g_bsum);
    float* out = (float*)d_out;

    const int nb = (M + SCAN_BLK - 1) / SCAN_BLK;

    // --- CSR build + dinv ---
    k_zero_deg<<<(M + 255) / 256, 256>>>(deg, M);
    k_count   <<<(E + 255) / 256, 256>>>(deg, dst, E);
    k_dinv    <<<(M + 255) / 256, 256>>>(dinv, deg, M);
    k_scan1   <<<nb, SCAN_BLK>>>(deg, off, bsum, M);
    k_scan2   <<<1, 32>>>(bsum, nb);
    k_scan3   <<<(M + 255) / 256, 256>>>(off, cur, bsum, M, E);
    k_place   <<<(E + 255) / 256, 256>>>(src, dst, cur, csr, E);

    dim3 gemm_grid2((M + 63) / 64, 2);  // N=128
    dim3 gemm_grid1((M + 63) / 64, 1);  // N=64

    // --- layer 1 ---
    k_gemm_k128<<<gemm_grid2, 256>>>(x, W1, h, dinv, M, 128, 0);
    k_agg128<<<(M * 32 + 255) / 256, 256>>>(h, off, csr, dinv, b1, agg, M);

    // --- layer 2 ---
    k_gemm_k128<<<gemm_grid2, 256>>>(agg, W2, h, dinv, M, 128, 1);
    k_agg128<<<(M * 32 + 255) / 256, 256>>>(h, off, csr, dinv, b2, agg, M);

    // --- layer 3 (N=64) ---
    k_gemm_k128<<<gemm_grid1, 256>>>(agg, W3, h, dinv, M, 64, 1);
    k_agg64<<<(M * 16 + 255) / 256, 256>>>(h, off, csr, dinv, b3, out, M);
}

// round 4
// speedup vs baseline: 1.9892x; 1.0042x over previous
#include <cuda_runtime.h>
#include <cstdint>
#include <cstddef>

// ---------------------------------------------------------------------------
// GCN, CSR-gather + high-efficiency FFMA SGEMM (tcgen05 unavailable: harness
// targets plain sm_100, which rejects all tcgen05.* instructions).
//   layer(X) = diag(dinv) * A_csr_sum( diag(dinv) * (relu(X) @ W) ) + b
// ---------------------------------------------------------------------------

#define MAX_NODES 100000
#define MAX_EDGES 1600000
#define SCAN_BLK  1024

__device__ float g_h  [(size_t)MAX_NODES * 128];
__device__ float g_agg[(size_t)MAX_NODES * 128];
__device__ int   g_deg [MAX_NODES];
__device__ float g_dinv[MAX_NODES];
__device__ int   g_off [MAX_NODES + 1];
__device__ int   g_cur [MAX_NODES];
__device__ int   g_csr [MAX_EDGES];
__device__ int   g_bsum[(MAX_NODES + SCAN_BLK - 1) / SCAN_BLK];

// ======================= CSR build =========================================
__global__ void k_zero_deg(int* deg, int n) {
    int i = blockIdx.x * blockDim.x + threadIdx.x;
    if (i < n) deg[i] = 0;
}
__global__ void k_count(int* deg, const int* __restrict__ dst, int E) {
    int e = blockIdx.x * blockDim.x + threadIdx.x;
    if (e < E) atomicAdd(&deg[dst[e]], 1);
}
__global__ void k_dinv(float* __restrict__ dinv, const int* __restrict__ deg, int n) {
    int i = blockIdx.x * blockDim.x + threadIdx.x;
    if (i < n) {
        int d = deg[i];
        dinv[i] = (d > 0) ? rsqrtf((float)d) : 0.0f;
    }
}
__global__ void __launch_bounds__(SCAN_BLK)
k_scan1(const int* __restrict__ deg, int* __restrict__ off, int* __restrict__ bsum, int n) {
    __shared__ int sh[SCAN_BLK];
    int i = blockIdx.x * SCAN_BLK + threadIdx.x;
    int x = (i < n) ? deg[i] : 0;
    sh[threadIdx.x] = x;
    __syncthreads();
#pragma unroll
    for (int s = 1; s < SCAN_BLK; s <<= 1) {
        int v = (threadIdx.x >= s) ? sh[threadIdx.x - s] : 0;
        __syncthreads();
        sh[threadIdx.x] += v;
        __syncthreads();
    }
    if (i < n) off[i] = sh[threadIdx.x] - x;
    if (threadIdx.x == SCAN_BLK - 1) bsum[blockIdx.x] = sh[threadIdx.x];
}
__global__ void k_scan2(int* bsum, int nb) {
    if (threadIdx.x == 0) {
        int run = 0;
        for (int b = 0; b < nb; b++) { int v = bsum[b]; bsum[b] = run; run += v; }
    }
}
__global__ void k_scan3(int* __restrict__ off, int* __restrict__ cur,
                        const int* __restrict__ bsum, int n, int E) {
    int i = blockIdx.x * blockDim.x + threadIdx.x;
    if (i < n) {
        int v = off[i] + bsum[i / SCAN_BLK];
        off[i] = v; cur[i] = v;
    }
    if (i == 0) off[n] = E;
}
__global__ void k_place(const int* __restrict__ src, const int* __restrict__ dst,
                        int* cur, int* __restrict__ csr, int E) {
    int e = blockIdx.x * blockDim.x + threadIdx.x;
    if (e < E) {
        int slot = atomicAdd(&cur[dst[e]], 1);
        csr[slot] = src[e];
    }
}

// ======================= FFMA SGEMM ========================================
// C[M,BN] = dinv[row] * ( (relu?)A[M,128] @ W[128,BN] ),  BN in {64,128}
// Block tile 128 x BN, BK=8, double-buffered smem, 8x8 split microtile
// (row halves +64, col halves +BN/2) -> all smem reads conflict-free.
template <int BN>
__global__ void __launch_bounds__(BN * 2, 512 / (BN * 2))
k_gemm_ffma(const float* __restrict__ A, const float* __restrict__ W,
            float* __restrict__ C, const float* __restrict__ dinv,
            int M, int relu_in) {
    constexpr int NT = BN * 2;         // 256 (BN=128) or 128 (BN=64)
    constexpr int TX = BN / 8;         // 16 or 8
    constexpr int HN = BN / 2;
    constexpr int NIT = 16;            // K=128 / BK=8

    __shared__ float As[2][8][132];    // [buf][k][m], padded
    __shared__ float Ws[2][8][BN];     // [buf][k][n]

    const int tid  = threadIdx.x;
    const int tx   = tid % TX;
    const int ty   = tid / TX;         // 0..15
    const int brow = blockIdx.x * 128;

    float acc[2][2][4][4];
#pragma unroll
    for (int a = 0; a < 2; a++)
#pragma unroll
        for (int b = 0; b < 2; b++)
#pragma unroll
            for (int i = 0; i < 4; i++)
#pragma unroll
                for (int j = 0; j < 4; j++) acc[a][b][i][j] = 0.0f;

    float4 areg[(BN == 64) ? 2 : 1];
    float4 wreg;

    // ---- global load of k-slab `it` into registers ----
    auto ldg = [&](int it) {
        const int k0 = it * 8;
        if (BN == 128) {
            int row = tid >> 1, kq = (tid & 1) * 4;
            int grow = brow + row;
            float4 v = make_float4(0.f, 0.f, 0.f, 0.f);
            if (grow < M) v = *(const float4*)(A + (size_t)grow * 128 + k0 + kq);
            areg[0] = v;
        } else {
            int grow = brow + tid;
            float4 v0 = make_float4(0.f, 0.f, 0.f, 0.f);
            float4 v1 = v0;
            if (grow < M) {
                v0 = *(const float4*)(A + (size_t)grow * 128 + k0);
                v1 = *(const float4*)(A + (size_t)grow * 128 + k0 + 4);
            }
            areg[0] = v0; areg[1] = v1;
        }
        if (relu_in) {
#pragma unroll
            for (int q = 0; q < ((BN == 64) ? 2 : 1); q++) {
                areg[q].x = fmaxf(areg[q].x, 0.f);
                areg[q].y = fmaxf(areg[q].y, 0.f);
                areg[q].z = fmaxf(areg[q].z, 0.f);
                areg[q].w = fmaxf(areg[q].w, 0.f);
            }
        }
        int wk = tid / (BN / 4);
        int wn = (tid % (BN / 4)) * 4;
        wreg = *(const float4*)(W + (size_t)(k0 + wk) * BN + wn);
    };

    // ---- store registers into smem buffer b ----
    auto sts = [&](int b) {
        if (BN == 128) {
            int row = tid >> 1, kq = (tid & 1) * 4;
            As[b][kq + 0][row] = areg[0].x;
            As[b][kq + 1][row] = areg[0].y;
            As[b][kq + 2][row] = areg[0].z;
            As[b][kq + 3][row] = areg[0].w;
        } else {
            int row = tid;
            As[b][0][row] = areg[0].x; As[b][1][row] = areg[0].y;
            As[b][2][row] = areg[0].z; As[b][3][row] = areg[0].w;
            As[b][4][row] = areg[1].x; As[b][5][row] = areg[1].y;
            As[b][6][row] = areg[1].z; As[b][7][row] = areg[1].w;
        }
        int wk = tid / (BN / 4);
        int wn = (tid % (BN / 4)) * 4;
        *(float4*)&Ws[b][wk][wn] = wreg;
    };

    ldg(0);
    sts(0);
    __syncthreads();

    for (int it = 0; it < NIT; it++) {
        const int cur = it & 1;
        if (it + 1 < NIT) ldg(it + 1);

#pragma unroll
        for (int kk = 0; kk < 8; kk++) {
            float a0[4], a1[4], b0[4], b1[4];
            *(float4*)a0 = *(const float4*)&As[cur][kk][ty * 4];
            *(float4*)a1 = *(const float4*)&As[cur][kk][ty * 4 + 64];
            *(float4*)b0 = *(const float4*)&Ws[cur][kk][tx * 4];
            *(float4*)b1 = *(const float4*)&Ws[cur][kk][tx * 4 + HN];
#pragma unroll
            for (int i = 0; i < 4; i++)
#pragma unroll
                for (int j = 0; j < 4; j++) {
                    acc[0][0][i][j] += a0[i] * b0[j];
                    acc[0][1][i][j] += a0[i] * b1[j];
                    acc[1][0][i][j] += a1[i] * b0[j];
                    acc[1][1][i][j] += a1[i] * b1[j];
                }
        }

        if (it + 1 < NIT) {
            sts(cur ^ 1);
            __syncthreads();
        }
    }

    // ---- epilogue: scale by dinv[row], store ----
#pragma unroll
    for (int rh = 0; rh < 2; rh++)
#pragma unroll
        for (int i = 0; i < 4; i++) {
            int row = brow + ty * 4 + rh * 64 + i;
            if (row < M) {
                float sc = __ldg(dinv + row);
                float* cp = C + (size_t)row * BN;
                float4 o0 = make_float4(acc[rh][0][i][0] * sc, acc[rh][0][i][1] * sc,
                                        acc[rh][0][i][2] * sc, acc[rh][0][i][3] * sc);
                float4 o1 = make_float4(acc[rh][1][i][0] * sc, acc[rh][1][i][1] * sc,
                                        acc[rh][1][i][2] * sc, acc[rh][1][i][3] * sc);
                *(float4*)(cp + tx * 4)      = o0;
                *(float4*)(cp + tx * 4 + HN) = o1;
            }
        }
}

// ===================== CSR gather-sum ======================================
__global__ void __launch_bounds__(256)
k_agg128(const float* __restrict__ h, const int* __restrict__ off,
         const int* __restrict__ csr, const float* __restrict__ dinv,
         const float* __restrict__ bias, float* __restrict__ out, int Nn) {
    int gt = blockIdx.x * blockDim.x + threadIdx.x;
    int node = gt >> 5;
    int lane = gt & 31;
    if (node >= Nn) return;
    int i  = __ldg(off + node);
    int s1 = __ldg(off + node + 1);

    float4 acc = make_float4(0.f, 0.f, 0.f, 0.f);
    for (; i + 4 <= s1; i += 4) {
        int sa = __ldg(csr + i);
        int sb = __ldg(csr + i + 1);
        int sc = __ldg(csr + i + 2);
        int sd = __ldg(csr + i + 3);
        float4 va = __ldg((const float4*)(h + (size_t)sa * 128) + lane);
        float4 vb = __ldg((const float4*)(h + (size_t)sb * 128) + lane);
        float4 vc = __ldg((const float4*)(h + (size_t)sc * 128) + lane);
        float4 vd = __ldg((const float4*)(h + (size_t)sd * 128) + lane);
        acc.x += (va.x + vb.x) + (vc.x + vd.x);
        acc.y += (va.y + vb.y) + (vc.y + vd.y);
        acc.z += (va.z + vb.z) + (vc.z + vd.z);
        acc.w += (va.w + vb.w) + (vc.w + vd.w);
    }
    for (; i < s1; i++) {
        int s = __ldg(csr + i);
        float4 v = __ldg((const float4*)(h + (size_t)s * 128) + lane);
        acc.x += v.x; acc.y += v.y; acc.z += v.z; acc.w += v.w;
    }
    float dv = __ldg(dinv + node);
    float4 bv = __ldg((const float4*)bias + lane);
    float4 o = make_float4(acc.x * dv + bv.x, acc.y * dv + bv.y,
                           acc.z * dv + bv.z, acc.w * dv + bv.w);
    *(float4*)(out + (size_t)node * 128 + lane * 4) = o;
}

__global__ void __launch_bounds__(256)
k_agg64(const float* __restrict__ h, const int* __restrict__ off,
        const int* __restrict__ csr, const float* __restrict__ dinv,
        const float* __restrict__ bias, float* __restrict__ out, int Nn) {
    int gt = blockIdx.x * blockDim.x + threadIdx.x;
    int node = gt >> 4;
    int lane = gt & 15;
    if (node >= Nn) return;
    int i  = __ldg(off + node);
    int s1 = __ldg(off + node + 1);

    float4 acc = make_float4(0.f, 0.f, 0.f, 0.f);
    for (; i + 4 <= s1; i += 4) {
        int sa = __ldg(csr + i);
        int sb = __ldg(csr + i + 1);
        int sc = __ldg(csr + i + 2);
        int sd = __ldg(csr + i + 3);
        float4 va = __ldg((const float4*)(h + (size_t)sa * 64) + lane);
        float4 vb = __ldg((const float4*)(h + (size_t)sb * 64) + lane);
        float4 vc = __ldg((const float4*)(h + (size_t)sc * 64) + lane);
        float4 vd = __ldg((const float4*)(h + (size_t)sd * 64) + lane);
        acc.x += (va.x + vb.x) + (vc.x + vd.x);
        acc.y += (va.y + vb.y) + (vc.y + vd.y);
        acc.z += (va.z + vb.z) + (vc.z + vd.z);
        acc.w += (va.w + vb.w) + (vc.w + vd.w);
    }
    for (; i < s1; i++) {
        int s = __ldg(csr + i);
        float4 v = __ldg((const float4*)(h + (size_t)s * 64) + lane);
        acc.x += v.x; acc.y += v.y; acc.z += v.z; acc.w += v.w;
    }
    float dv = __ldg(dinv + node);
    float4 bv = __ldg((const float4*)bias + lane);
    float4 o = make_float4(acc.x * dv + bv.x, acc.y * dv + bv.y,
                           acc.z * dv + bv.z, acc.w * dv + bv.w);
    *(float4*)(out + (size_t)node * 64 + lane * 4) = o;
}

// ---------------------------------------------------------------------------
extern "C" void kernel_launch(void* const* d_in, const int* in_sizes, int n_in,
                              void* d_out, int out_size) {
    const float* x  = (const float*)d_in[0];
    const int*   ei = (const int*)  d_in[1];
    const float* W1 = (const float*)d_in[2];
    const float* b1 = (const float*)d_in[3];
    const float* W2 = (const float*)d_in[4];
    const float* b2 = (const float*)d_in[5];
    const float* W3 = (const float*)d_in[6];
    const float* b3 = (const float*)d_in[7];

    const int E = in_sizes[1] / 2;
    const int M = in_sizes[0] / 128;
    const int* src = ei;
    const int* dst = ei + E;

    float *h, *agg, *dinv;
    int *deg, *off, *cur, *csr, *bsum;
    cudaGetSymbolAddress((void**)&h,    g_h);
    cudaGetSymbolAddress((void**)&agg,  g_agg);
    cudaGetSymbolAddress((void**)&deg,  g_deg);
    cudaGetSymbolAddress((void**)&dinv, g_dinv);
    cudaGetSymbolAddress((void**)&off,  g_off);
    cudaGetSymbolAddress((void**)&cur,  g_cur);
    cudaGetSymbolAddress((void**)&csr,  g_csr);
    cudaGetSymbolAddress((void**)&bsum, g_bsum);
    float* out = (float*)d_out;

    const int nb = (M + SCAN_BLK - 1) / SCAN_BLK;

    // --- CSR build + dinv ---
    k_zero_deg<<<(M + 255) / 256, 256>>>(deg, M);
    k_count   <<<(E + 255) / 256, 256>>>(deg, dst, E);
    k_dinv    <<<(M + 255) / 256, 256>>>(dinv, deg, M);
    k_scan1   <<<nb, SCAN_BLK>>>(deg, off, bsum, M);
    k_scan2   <<<1, 32>>>(bsum, nb);
    k_scan3   <<<(M + 255) / 256, 256>>>(off, cur, bsum, M, E);
    k_place   <<<(E + 255) / 256, 256>>>(src, dst, cur, csr, E);

    const int gtiles = (M + 127) / 128;

    // --- layer 1 ---
    k_gemm_ffma<128><<<gtiles, 256>>>(x, W1, h, dinv, M, 0);
    k_agg128<<<(M * 32 + 255) / 256, 256>>>(h, off, csr, dinv, b1, agg, M);

    // --- layer 2 ---
    k_gemm_ffma<128><<<gtiles, 256>>>(agg, W2, h, dinv, M, 1);
    k_agg128<<<(M * 32 + 255) / 256, 256>>>(h, off, csr, dinv, b2, agg, M);

    // --- layer 3 (N=64) ---
    k_gemm_ffma<64><<<gtiles, 128>>>(agg, W3, h, dinv, M, 1);
    k_agg64<<<(M * 16 + 255) / 256, 256>>>(h, off, csr, dinv, b3, out, M);
}

// round 5
// speedup vs baseline: 2.1554x; 1.0835x over previous
#include <cuda_runtime.h>
#include <cuda_fp16.h>
#include <cstdint>
#include <cstddef>

// ---------------------------------------------------------------------------
// GCN, CSR-gather formulation. Aggregation is L2-BW bound -> gather in fp16
// (h stored as half), accumulate fp32. GEMM in fp32 FFMA (tcgen05 rejected by
// harness's plain sm_100 ptxas target).
//   layer(X) = diag(dinv) * A_csr_sum( fp16(diag(dinv) * (relu(X) @ W)) ) + b
// ---------------------------------------------------------------------------

#define MAX_NODES 100000
#define MAX_EDGES 1600000
#define SCAN_BLK  1024

__device__ __half g_h [(size_t)MAX_NODES * 128];   // fp16 gather source
__device__ float g_agg[(size_t)MAX_NODES * 128];   // fp32 agg / GEMM input
__device__ int   g_deg [MAX_NODES];
__device__ float g_dinv[MAX_NODES];
__device__ int   g_off [MAX_NODES + 1];
__device__ int   g_cur [MAX_NODES];
__device__ int   g_csr [MAX_EDGES];
__device__ int   g_bsum[(MAX_NODES + SCAN_BLK - 1) / SCAN_BLK];

// ======================= CSR build =========================================
__global__ void k_zero_deg(int* deg, int n) {
    int i = blockIdx.x * blockDim.x + threadIdx.x;
    if (i < n) deg[i] = 0;
}
__global__ void k_count(int* deg, const int* __restrict__ dst, int E) {
    int e = blockIdx.x * blockDim.x + threadIdx.x;
    if (e < E) atomicAdd(&deg[dst[e]], 1);
}
__global__ void k_dinv(float* __restrict__ dinv, const int* __restrict__ deg, int n) {
    int i = blockIdx.x * blockDim.x + threadIdx.x;
    if (i < n) {
        int d = deg[i];
        dinv[i] = (d > 0) ? rsqrtf((float)d) : 0.0f;
    }
}
__global__ void __launch_bounds__(SCAN_BLK)
k_scan1(const int* __restrict__ deg, int* __restrict__ off, int* __restrict__ bsum, int n) {
    __shared__ int sh[SCAN_BLK];
    int i = blockIdx.x * SCAN_BLK + threadIdx.x;
    int x = (i < n) ? deg[i] : 0;
    sh[threadIdx.x] = x;
    __syncthreads();
#pragma unroll
    for (int s = 1; s < SCAN_BLK; s <<= 1) {
        int v = (threadIdx.x >= s) ? sh[threadIdx.x - s] : 0;
        __syncthreads();
        sh[threadIdx.x] += v;
        __syncthreads();
    }
    if (i < n) off[i] = sh[threadIdx.x] - x;
    if (threadIdx.x == SCAN_BLK - 1) bsum[blockIdx.x] = sh[threadIdx.x];
}
__global__ void k_scan2(int* bsum, int nb) {
    if (threadIdx.x == 0) {
        int run = 0;
        for (int b = 0; b < nb; b++) { int v = bsum[b]; bsum[b] = run; run += v; }
    }
}
__global__ void k_scan3(int* __restrict__ off, int* __restrict__ cur,
                        const int* __restrict__ bsum, int n, int E) {
    int i = blockIdx.x * blockDim.x + threadIdx.x;
    if (i < n) {
        int v = off[i] + bsum[i / SCAN_BLK];
        off[i] = v; cur[i] = v;
    }
    if (i == 0) off[n] = E;
}
__global__ void k_place(const int* __restrict__ src, const int* __restrict__ dst,
                        int* cur, int* __restrict__ csr, int E) {
    int e = blockIdx.x * blockDim.x + threadIdx.x;
    if (e < E) {
        int slot = atomicAdd(&cur[dst[e]], 1);
        csr[slot] = src[e];
    }
}

// ======================= FFMA SGEMM, fp16 output ===========================
// Chalf[M,BN] = fp16( dinv[row] * ( (relu?)A[M,128] @ W[128,BN] ) )
template <int BN>
__global__ void __launch_bounds__(BN * 2, 512 / (BN * 2))
k_gemm_ffma(const float* __restrict__ A, const float* __restrict__ W,
            __half* __restrict__ C, const float* __restrict__ dinv,
            int M, int relu_in) {
    constexpr int TX = BN / 8;
    constexpr int HN = BN / 2;
    constexpr int NIT = 16;

    __shared__ float As[2][8][132];
    __shared__ float Ws[2][8][BN];

    const int tid  = threadIdx.x;
    const int tx   = tid % TX;
    const int ty   = tid / TX;
    const int brow = blockIdx.x * 128;

    float acc[2][2][4][4];
#pragma unroll
    for (int a = 0; a < 2; a++)
#pragma unroll
        for (int b = 0; b < 2; b++)
#pragma unroll
            for (int i = 0; i < 4; i++)
#pragma unroll
                for (int j = 0; j < 4; j++) acc[a][b][i][j] = 0.0f;

    float4 areg[(BN == 64) ? 2 : 1];
    float4 wreg;

    auto ldg = [&](int it) {
        const int k0 = it * 8;
        if (BN == 128) {
            int row = tid >> 1, kq = (tid & 1) * 4;
            int grow = brow + row;
            float4 v = make_float4(0.f, 0.f, 0.f, 0.f);
            if (grow < M) v = *(const float4*)(A + (size_t)grow * 128 + k0 + kq);
            areg[0] = v;
        } else {
            int grow = brow + tid;
            float4 v0 = make_float4(0.f, 0.f, 0.f, 0.f);
            float4 v1 = v0;
            if (grow < M) {
                v0 = *(const float4*)(A + (size_t)grow * 128 + k0);
                v1 = *(const float4*)(A + (size_t)grow * 128 + k0 + 4);
            }
            areg[0] = v0; areg[1] = v1;
        }
        if (relu_in) {
#pragma unroll
            for (int q = 0; q < ((BN == 64) ? 2 : 1); q++) {
                areg[q].x = fmaxf(areg[q].x, 0.f);
                areg[q].y = fmaxf(areg[q].y, 0.f);
                areg[q].z = fmaxf(areg[q].z, 0.f);
                areg[q].w = fmaxf(areg[q].w, 0.f);
            }
        }
        int wk = tid / (BN / 4);
        int wn = (tid % (BN / 4)) * 4;
        wreg = *(const float4*)(W + (size_t)(k0 + wk) * BN + wn);
    };

    auto sts = [&](int b) {
        if (BN == 128) {
            int row = tid >> 1, kq = (tid & 1) * 4;
            As[b][kq + 0][row] = areg[0].x;
            As[b][kq + 1][row] = areg[0].y;
            As[b][kq + 2][row] = areg[0].z;
            As[b][kq + 3][row] = areg[0].w;
        } else {
            int row = tid;
            As[b][0][row] = areg[0].x; As[b][1][row] = areg[0].y;
            As[b][2][row] = areg[0].z; As[b][3][row] = areg[0].w;
            As[b][4][row] = areg[1].x; As[b][5][row] = areg[1].y;
            As[b][6][row] = areg[1].z; As[b][7][row] = areg[1].w;
        }
        int wk = tid / (BN / 4);
        int wn = (tid % (BN / 4)) * 4;
        *(float4*)&Ws[b][wk][wn] = wreg;
    };

    ldg(0);
    sts(0);
    __syncthreads();

    for (int it = 0; it < NIT; it++) {
        const int cur = it & 1;
        if (it + 1 < NIT) ldg(it + 1);

#pragma unroll
        for (int kk = 0; kk < 8; kk++) {
            float a0[4], a1[4], b0[4], b1[4];
            *(float4*)a0 = *(const float4*)&As[cur][kk][ty * 4];
            *(float4*)a1 = *(const float4*)&As[cur][kk][ty * 4 + 64];
            *(float4*)b0 = *(const float4*)&Ws[cur][kk][tx * 4];
            *(float4*)b1 = *(const float4*)&Ws[cur][kk][tx * 4 + HN];
#pragma unroll
            for (int i = 0; i < 4; i++)
#pragma unroll
                for (int j = 0; j < 4; j++) {
                    acc[0][0][i][j] += a0[i] * b0[j];
                    acc[0][1][i][j] += a0[i] * b1[j];
                    acc[1][0][i][j] += a1[i] * b0[j];
                    acc[1][1][i][j] += a1[i] * b1[j];
                }
        }

        if (it + 1 < NIT) {
            sts(cur ^ 1);
            __syncthreads();
        }
    }

    // epilogue: scale by dinv, convert to fp16, store 4 halves (8B) per frag
#pragma unroll
    for (int rh = 0; rh < 2; rh++)
#pragma unroll
        for (int i = 0; i < 4; i++) {
            int row = brow + ty * 4 + rh * 64 + i;
            if (row < M) {
                float sc = __ldg(dinv + row);
                __half* cp = C + (size_t)row * BN;
                __half2 p00 = __floats2half2_rn(acc[rh][0][i][0] * sc, acc[rh][0][i][1] * sc);
                __half2 p01 = __floats2half2_rn(acc[rh][0][i][2] * sc, acc[rh][0][i][3] * sc);
                __half2 p10 = __floats2half2_rn(acc[rh][1][i][0] * sc, acc[rh][1][i][1] * sc);
                __half2 p11 = __floats2half2_rn(acc[rh][1][i][2] * sc, acc[rh][1][i][3] * sc);
                *(__half2*)(cp + tx * 4)          = p00;
                *(__half2*)(cp + tx * 4 + 2)      = p01;
                *(__half2*)(cp + tx * 4 + HN)     = p10;
                *(__half2*)(cp + tx * 4 + HN + 2) = p11;
            }
        }
}

// ===================== CSR gather-sum (fp16 in, fp32 out) ==================
// C=128: warp per node, lane covers 4 halves (8B). 4x edge unroll.
__global__ void __launch_bounds__(256)
k_agg128(const __half* __restrict__ h, const int* __restrict__ off,
         const int* __restrict__ csr, const float* __restrict__ dinv,
         const float* __restrict__ bias, float* __restrict__ out, int Nn) {
    int gt = blockIdx.x * blockDim.x + threadIdx.x;
    int node = gt >> 5;
    int lane = gt & 31;
    if (node >= Nn) return;
    int i  = __ldg(off + node);
    int s1 = __ldg(off + node + 1);

    float4 acc = make_float4(0.f, 0.f, 0.f, 0.f);
#pragma unroll 1
    for (; i + 4 <= s1; i += 4) {
        int sa = __ldg(csr + i);
        int sb = __ldg(csr + i + 1);
        int sc = __ldg(csr + i + 2);
        int sd = __ldg(csr + i + 3);
        __half2 a0 = __ldg((const __half2*)(h + (size_t)sa * 128) + lane * 2);
        __half2 a1 = __ldg((const __half2*)(h + (size_t)sa * 128) + lane * 2 + 1);
        __half2 b0 = __ldg((const __half2*)(h + (size_t)sb * 128) + lane * 2);
        __half2 b1 = __ldg((const __half2*)(h + (size_t)sb * 128) + lane * 2 + 1);
        __half2 c0 = __ldg((const __half2*)(h + (size_t)sc * 128) + lane * 2);
        __half2 c1 = __ldg((const __half2*)(h + (size_t)sc * 128) + lane * 2 + 1);
        __half2 d0 = __ldg((const __half2*)(h + (size_t)sd * 128) + lane * 2);
        __half2 d1 = __ldg((const __half2*)(h + (size_t)sd * 128) + lane * 2 + 1);
        float2 fa0 = __half22float2(a0), fa1 = __half22float2(a1);
        float2 fb0 = __half22float2(b0), fb1 = __half22float2(b1);
        float2 fc0 = __half22float2(c0), fc1 = __half22float2(c1);
        float2 fd0 = __half22float2(d0), fd1 = __half22float2(d1);
        acc.x += (fa0.x + fb0.x) + (fc0.x + fd0.x);
        acc.y += (fa0.y + fb0.y) + (fc0.y + fd0.y);
        acc.z += (fa1.x + fb1.x) + (fc1.x + fd1.x);
        acc.w += (fa1.y + fb1.y) + (fc1.y + fd1.y);
    }
    for (; i < s1; i++) {
        int s = __ldg(csr + i);
        __half2 v0 = __ldg((const __half2*)(h + (size_t)s * 128) + lane * 2);
        __half2 v1 = __ldg((const __half2*)(h + (size_t)s * 128) + lane * 2 + 1);
        float2 f0 = __half22float2(v0), f1 = __half22float2(v1);
        acc.x += f0.x; acc.y += f0.y; acc.z += f1.x; acc.w += f1.y;
    }
    float dv = __ldg(dinv + node);
    float4 bv = __ldg((const float4*)bias + lane);
    float4 o = make_float4(acc.x * dv + bv.x, acc.y * dv + bv.y,
                           acc.z * dv + bv.z, acc.w * dv + bv.w);
    *(float4*)(out + (size_t)node * 128 + lane * 4) = o;
}

// C=64: 16 lanes per node
__global__ void __launch_bounds__(256)
k_agg64(const __half* __restrict__ h, const int* __restrict__ off,
        const int* __restrict__ csr, const float* __restrict__ dinv,
        const float* __restrict__ bias, float* __restrict__ out, int Nn) {
    int gt = blockIdx.x * blockDim.x + threadIdx.x;
    int node = gt >> 4;
    int lane = gt & 15;
    if (node >= Nn) return;
    int i  = __ldg(off + node);
    int s1 = __ldg(off + node + 1);

    float4 acc = make_float4(0.f, 0.f, 0.f, 0.f);
#pragma unroll 1
    for (; i + 4 <= s1; i += 4) {
        int sa = __ldg(csr + i);
        int sb = __ldg(csr + i + 1);
        int sc = __ldg(csr + i + 2);
        int sd = __ldg(csr + i + 3);
        __half2 a0 = __ldg((const __half2*)(h + (size_t)sa * 64) + lane * 2);
        __half2 a1 = __ldg((const __half2*)(h + (size_t)sa * 64) + lane * 2 + 1);
        __half2 b0 = __ldg((const __half2*)(h + (size_t)sb * 64) + lane * 2);
        __half2 b1 = __ldg((const __half2*)(h + (size_t)sb * 64) + lane * 2 + 1);
        __half2 c0 = __ldg((const __half2*)(h + (size_t)sc * 64) + lane * 2);
        __half2 c1 = __ldg((const __half2*)(h + (size_t)sc * 64) + lane * 2 + 1);
        __half2 d0 = __ldg((const __half2*)(h + (size_t)sd * 64) + lane * 2);
        __half2 d1 = __ldg((const __half2*)(h + (size_t)sd * 64) + lane * 2 + 1);
        float2 fa0 = __half22float2(a0), fa1 = __half22float2(a1);
        float2 fb0 = __half22float2(b0), fb1 = __half22float2(b1);
        float2 fc0 = __half22float2(c0), fc1 = __half22float2(c1);
        float2 fd0 = __half22float2(d0), fd1 = __half22float2(d1);
        acc.x += (fa0.x + fb0.x) + (fc0.x + fd0.x);
        acc.y += (fa0.y + fb0.y) + (fc0.y + fd0.y);
        acc.z += (fa1.x + fb1.x) + (fc1.x + fd1.x);
        acc.w += (fa1.y + fb1.y) + (fc1.y + fd1.y);
    }
    for (; i < s1; i++) {
        int s = __ldg(csr + i);
        __half2 v0 = __ldg((const __half2*)(h + (size_t)s * 64) + lane * 2);
        __half2 v1 = __ldg((const __half2*)(h + (size_t)s * 64) + lane * 2 + 1);
        float2 f0 = __half22float2(v0), f1 = __half22float2(v1);
        acc.x += f0.x; acc.y += f0.y; acc.z += f1.x; acc.w += f1.y;
    }
    float dv = __ldg(dinv + node);
    float4 bv = __ldg((const float4*)bias + lane);
    float4 o = make_float4(acc.x * dv + bv.x, acc.y * dv + bv.y,
                           acc.z * dv + bv.z, acc.w * dv + bv.w);
    *(float4*)(out + (size_t)node * 64 + lane * 4) = o;
}

// ---------------------------------------------------------------------------
extern "C" void kernel_launch(void* const* d_in, const int* in_sizes, int n_in,
                              void* d_out, int out_size) {
    const float* x  = (const float*)d_in[0];
    const int*   ei = (const int*)  d_in[1];
    const float* W1 = (const float*)d_in[2];
    const float* b1 = (const float*)d_in[3];
    const float* W2 = (const float*)d_in[4];
    const float* b2 = (const float*)d_in[5];
    const float* W3 = (const float*)d_in[6];
    const float* b3 = (const float*)d_in[7];

    const int E = in_sizes[1] / 2;
    const int M = in_sizes[0] / 128;
    const int* src = ei;
    const int* dst = ei + E;

    __half* h;
    float *agg, *dinv;
    int *deg, *off, *cur, *csr, *bsum;
    cudaGetSymbolAddress((void**)&h,    g_h);
    cudaGetSymbolAddress((void**)&agg,  g_agg);
    cudaGetSymbolAddress((void**)&deg,  g_deg);
    cudaGetSymbolAddress((void**)&dinv, g_dinv);
    cudaGetSymbolAddress((void**)&off,  g_off);
    cudaGetSymbolAddress((void**)&cur,  g_cur);
    cudaGetSymbolAddress((void**)&csr,  g_csr);
    cudaGetSymbolAddress((void**)&bsum, g_bsum);
    float* out = (float*)d_out;

    const int nb = (M + SCAN_BLK - 1) / SCAN_BLK;

    // --- CSR build + dinv ---
    k_zero_deg<<<(M + 255) / 256, 256>>>(deg, M);
    k_count   <<<(E + 255) / 256, 256>>>(deg, dst, E);
    k_dinv    <<<(M + 255) / 256, 256>>>(dinv, deg, M);
    k_scan1   <<<nb, SCAN_BLK>>>(deg, off, bsum, M);
    k_scan2   <<<1, 32>>>(bsum, nb);
    k_scan3   <<<(M + 255) / 256, 256>>>(off, cur, bsum, M, E);
    k_place   <<<(E + 255) / 256, 256>>>(src, dst, cur, csr, E);

    const int gtiles = (M + 127) / 128;

    // --- layer 1 ---
    k_gemm_ffma<128><<<gtiles, 256>>>(x, W1, h, dinv, M, 0);
    k_agg128<<<(M * 32 + 255) / 256, 256>>>(h, off, csr, dinv, b1, agg, M);

    // --- layer 2 ---
    k_gemm_ffma<128><<<gtiles, 256>>>(agg, W2, h, dinv, M, 1);
    k_agg128<<<(M * 32 + 255) / 256, 256>>>(h, off, csr, dinv, b2, agg, M);

    // --- layer 3 (N=64) ---
    k_gemm_ffma<64><<<gtiles, 128>>>(agg, W3, h, dinv, M, 1);
    k_agg64<<<(M * 16 + 255) / 256, 256>>>(h, off, csr, dinv, b3, out, M);
}

// round 6
// speedup vs baseline: 2.2996x; 1.0669x over previous
#include <cuda_runtime.h>
#include <cuda_fp16.h>
#include <cstdint>
#include <cstddef>

// ---------------------------------------------------------------------------
// GCN, CSR-gather + legacy-HMMA (mma.sync fp16, f32 accum) GEMM.
// tcgen05 rejected by harness's plain sm_100 ptxas target; FFMA is rt=2
// (structural ~18 TMAC/s) and was the bottleneck. mma.sync.m16n8k16 is
// standard PTX and runs on the tensor pipe.
//   layer(X) = diag(dinv) * A_csr_sum( fp16(diag(dinv) * (relu(X) @ W)) ) + b
// ---------------------------------------------------------------------------

#define MAX_NODES 100000
#define MAX_EDGES 1600000
#define SCAN_BLK  1024

__device__ __half g_h [(size_t)MAX_NODES * 128];   // fp16 gather source
__device__ float g_agg[(size_t)MAX_NODES * 128];   // fp32 agg / GEMM input
__device__ int   g_deg [MAX_NODES];
__device__ float g_dinv[MAX_NODES];
__device__ int   g_off [MAX_NODES + 1];
__device__ int   g_cur [MAX_NODES];
__device__ int   g_csr [MAX_EDGES];
__device__ int   g_bsum[(MAX_NODES + SCAN_BLK - 1) / SCAN_BLK];

// ======================= CSR build =========================================
__global__ void k_zero_deg(int* deg, int n) {
    int i = blockIdx.x * blockDim.x + threadIdx.x;
    if (i < n) deg[i] = 0;
}
__global__ void k_count(int* deg, const int* __restrict__ dst, int E) {
    int e = blockIdx.x * blockDim.x + threadIdx.x;
    if (e < E) atomicAdd(&deg[dst[e]], 1);
}
__global__ void k_dinv(float* __restrict__ dinv, const int* __restrict__ deg, int n) {
    int i = blockIdx.x * blockDim.x + threadIdx.x;
    if (i < n) {
        int d = deg[i];
        dinv[i] = (d > 0) ? rsqrtf((float)d) : 0.0f;
    }
}
__global__ void __launch_bounds__(SCAN_BLK)
k_scan1(const int* __restrict__ deg, int* __restrict__ off, int* __restrict__ bsum, int n) {
    __shared__ int sh[SCAN_BLK];
    int i = blockIdx.x * SCAN_BLK + threadIdx.x;
    int x = (i < n) ? deg[i] : 0;
    sh[threadIdx.x] = x;
    __syncthreads();
#pragma unroll
    for (int s = 1; s < SCAN_BLK; s <<= 1) {
        int v = (threadIdx.x >= s) ? sh[threadIdx.x - s] : 0;
        __syncthreads();
        sh[threadIdx.x] += v;
        __syncthreads();
    }
    if (i < n) off[i] = sh[threadIdx.x] - x;
    if (threadIdx.x == SCAN_BLK - 1) bsum[blockIdx.x] = sh[threadIdx.x];
}
__global__ void k_scan2(int* bsum, int nb) {
    if (threadIdx.x == 0) {
        int run = 0;
        for (int b = 0; b < nb; b++) { int v = bsum[b]; bsum[b] = run; run += v; }
    }
}
__global__ void k_scan3(int* __restrict__ off, int* __restrict__ cur,
                        const int* __restrict__ bsum, int n, int E) {
    int i = blockIdx.x * blockDim.x + threadIdx.x;
    if (i < n) {
        int v = off[i] + bsum[i / SCAN_BLK];
        off[i] = v; cur[i] = v;
    }
    if (i == 0) off[n] = E;
}
__global__ void k_place(const int* __restrict__ src, const int* __restrict__ dst,
                        int* cur, int* __restrict__ csr, int E) {
    int e = blockIdx.x * blockDim.x + threadIdx.x;
    if (e < E) {
        int slot = atomicAdd(&cur[dst[e]], 1);
        csr[slot] = src[e];
    }
}

// ======================= HMMA GEMM =========================================
// Chalf[M,BN] = fp16( dinv[row] * ( (relu?)A[M,128] @ W[128,BN] ) )
// Block: 128 rows x BN cols, whole K=128 in smem (A fp16 + W^T fp16).
// Warps: 2(M) x BN/32(N); warp tile 64x32; mma.sync.m16n8k16.f32.f16.f16.f32.
#define APITCH 136   // halves per smem row (272B; rows offset 4 banks -> ldmatrix conflict-free)

__device__ __forceinline__ void ldmx4(uint32_t* r, uint32_t addr) {
    asm volatile("ldmatrix.sync.aligned.m8n8.x4.shared.b16 {%0,%1,%2,%3}, [%4];"
                 : "=r"(r[0]), "=r"(r[1]), "=r"(r[2]), "=r"(r[3]) : "r"(addr));
}
__device__ __forceinline__ void ldmx2(uint32_t* r, uint32_t addr) {
    asm volatile("ldmatrix.sync.aligned.m8n8.x2.shared.b16 {%0,%1}, [%2];"
                 : "=r"(r[0]), "=r"(r[1]) : "r"(addr));
}
__device__ __forceinline__ void mma16816(float* c, const uint32_t* a, const uint32_t* b) {
    asm volatile("mma.sync.aligned.m16n8k16.row.col.f32.f16.f16.f32 "
                 "{%0,%1,%2,%3}, {%4,%5,%6,%7}, {%8,%9}, {%0,%1,%2,%3};"
                 : "+f"(c[0]), "+f"(c[1]), "+f"(c[2]), "+f"(c[3])
                 : "r"(a[0]), "r"(a[1]), "r"(a[2]), "r"(a[3]), "r"(b[0]), "r"(b[1]));
}

template <int BN>
__global__ void __launch_bounds__(BN * 2)
k_gemm_hmma(const float* __restrict__ A, const float* __restrict__ W,
            __half* __restrict__ C, const float* __restrict__ dinv,
            int M, int relu_in) {
    constexpr int NT = BN * 2;        // threads: 256 (BN=128) / 128 (BN=64)
    constexpr int NWN = BN / 32;      // N-warps: 4 / 2

    extern __shared__ __half sm[];
    __half* As = sm;                              // [128][APITCH]
    __half* Wt = sm + 128 * APITCH;               // [BN][APITCH]  (W transposed: [n][k])

    const int tid  = threadIdx.x;
    const int wid  = tid >> 5;
    const int lane = tid & 31;
    const int wm   = wid / NWN;       // 0..1
    const int wn   = wid % NWN;       // 0..NWN-1
    const int brow = blockIdx.x * 128;

    // ---- load A (fp32 -> fp16, relu folded) ----
    for (int idx = tid; idx < 128 * 32; idx += NT) {   // 32 float4 per row
        int row  = idx >> 5;
        int col4 = (idx & 31) * 4;
        int grow = brow + row;
        float4 v = make_float4(0.f, 0.f, 0.f, 0.f);
        if (grow < M) v = *(const float4*)(A + (size_t)grow * 128 + col4);
        if (relu_in) {
            v.x = fmaxf(v.x, 0.f); v.y = fmaxf(v.y, 0.f);
            v.z = fmaxf(v.z, 0.f); v.w = fmaxf(v.w, 0.f);
        }
        __half2* p = (__half2*)(As + row * APITCH + col4);
        p[0] = __floats2half2_rn(v.x, v.y);
        p[1] = __floats2half2_rn(v.z, v.w);
    }
    // ---- load W [128 x BN] fp32 -> Wt [BN][128] fp16 ----
    for (int idx = tid; idx < 128 * (BN / 4); idx += NT) {
        int k  = idx / (BN / 4);
        int n0 = (idx % (BN / 4)) * 4;
        float4 v = *(const float4*)(W + (size_t)k * BN + n0);
        Wt[(n0 + 0) * APITCH + k] = __float2half_rn(v.x);
        Wt[(n0 + 1) * APITCH + k] = __float2half_rn(v.y);
        Wt[(n0 + 2) * APITCH + k] = __float2half_rn(v.z);
        Wt[(n0 + 3) * APITCH + k] = __float2half_rn(v.w);
    }
    __syncthreads();

    const uint32_t asb = (uint32_t)__cvta_generic_to_shared(As);
    const uint32_t wsb = (uint32_t)__cvta_generic_to_shared(Wt);

    float acc[4][4][4];               // [m-frag][n-frag][c0..c3]
#pragma unroll
    for (int i = 0; i < 4; i++)
#pragma unroll
        for (int j = 0; j < 4; j++)
#pragma unroll
            for (int q = 0; q < 4; q++) acc[i][j][q] = 0.0f;

    // per-lane ldmatrix base offsets
    const int aRow0 = wm * 64 + (lane & 15);     // + mf*16
    const int aKoff = (lane >> 4) * 8;           // + ks*16
    const int bRow0 = wn * 32 + (lane & 7);      // + nf*8
    const int bKoff = ((lane >> 3) & 1) * 8;     // + ks*16

#pragma unroll
    for (int ks = 0; ks < 8; ks++) {
        uint32_t a[4][4], b[4][2];
#pragma unroll
        for (int mf = 0; mf < 4; mf++)
            ldmx4(a[mf], asb + (uint32_t)(((aRow0 + mf * 16) * APITCH) + ks * 16 + aKoff) * 2);
#pragma unroll
        for (int nf = 0; nf < 4; nf++)
            ldmx2(b[nf], wsb + (uint32_t)(((bRow0 + nf * 8) * APITCH) + ks * 16 + bKoff) * 2);
#pragma unroll
        for (int mf = 0; mf < 4; mf++)
#pragma unroll
            for (int nf = 0; nf < 4; nf++)
                mma16816(acc[mf][nf], a[mf], b[nf]);
    }

    // ---- epilogue: dinv scale, fp16 store ----
    const int rbase = brow + wm * 64 + (lane >> 2);
    const int cbase = wn * 32 + (lane & 3) * 2;
#pragma unroll
    for (int mf = 0; mf < 4; mf++) {
        int r0 = rbase + mf * 16;
        int r1 = r0 + 8;
        float s0 = (r0 < M) ? __ldg(dinv + r0) : 0.0f;
        float s1 = (r1 < M) ? __ldg(dinv + r1) : 0.0f;
#pragma unroll
        for (int nf = 0; nf < 4; nf++) {
            int col = cbase + nf * 8;
            if (r0 < M)
                *(__half2*)(C + (size_t)r0 * BN + col) =
                    __floats2half2_rn(acc[mf][nf][0] * s0, acc[mf][nf][1] * s0);
            if (r1 < M)
                *(__half2*)(C + (size_t)r1 * BN + col) =
                    __floats2half2_rn(acc[mf][nf][2] * s1, acc[mf][nf][3] * s1);
        }
    }
}

// ===================== CSR gather-sum (fp16 in, fp32 out) ==================
__global__ void __launch_bounds__(256)
k_agg128(const __half* __restrict__ h, const int* __restrict__ off,
         const int* __restrict__ csr, const float* __restrict__ dinv,
         const float* __restrict__ bias, float* __restrict__ out, int Nn) {
    int gt = blockIdx.x * blockDim.x + threadIdx.x;
    int node = gt >> 5;
    int lane = gt & 31;
    if (node >= Nn) return;
    int i  = __ldg(off + node);
    int s1 = __ldg(off + node + 1);

    float4 acc = make_float4(0.f, 0.f, 0.f, 0.f);
#pragma unroll 1
    for (; i + 4 <= s1; i += 4) {
        int sa = __ldg(csr + i);
        int sb = __ldg(csr + i + 1);
        int sc = __ldg(csr + i + 2);
        int sd = __ldg(csr + i + 3);
        __half2 a0 = __ldg((const __half2*)(h + (size_t)sa * 128) + lane * 2);
        __half2 a1 = __ldg((const __half2*)(h + (size_t)sa * 128) + lane * 2 + 1);
        __half2 b0 = __ldg((const __half2*)(h + (size_t)sb * 128) + lane * 2);
        __half2 b1 = __ldg((const __half2*)(h + (size_t)sb * 128) + lane * 2 + 1);
        __half2 c0 = __ldg((const __half2*)(h + (size_t)sc * 128) + lane * 2);
        __half2 c1 = __ldg((const __half2*)(h + (size_t)sc * 128) + lane * 2 + 1);
        __half2 d0 = __ldg((const __half2*)(h + (size_t)sd * 128) + lane * 2);
        __half2 d1 = __ldg((const __half2*)(h + (size_t)sd * 128) + lane * 2 + 1);
        float2 fa0 = __half22float2(a0), fa1 = __half22float2(a1);
        float2 fb0 = __half22float2(b0), fb1 = __half22float2(b1);
        float2 fc0 = __half22float2(c0), fc1 = __half22float2(c1);
        float2 fd0 = __half22float2(d0), fd1 = __half22float2(d1);
        acc.x += (fa0.x + fb0.x) + (fc0.x + fd0.x);
        acc.y += (fa0.y + fb0.y) + (fc0.y + fd0.y);
        acc.z += (fa1.x + fb1.x) + (fc1.x + fd1.x);
        acc.w += (fa1.y + fb1.y) + (fc1.y + fd1.y);
    }
    for (; i < s1; i++) {
        int s = __ldg(csr + i);
        __half2 v0 = __ldg((const __half2*)(h + (size_t)s * 128) + lane * 2);
        __half2 v1 = __ldg((const __half2*)(h + (size_t)s * 128) + lane * 2 + 1);
        float2 f0 = __half22float2(v0), f1 = __half22float2(v1);
        acc.x += f0.x; acc.y += f0.y; acc.z += f1.x; acc.w += f1.y;
    }
    float dv = __ldg(dinv + node);
    float4 bv = __ldg((const float4*)bias + lane);
    float4 o = make_float4(acc.x * dv + bv.x, acc.y * dv + bv.y,
                           acc.z * dv + bv.z, acc.w * dv + bv.w);
    *(float4*)(out + (size_t)node * 128 + lane * 4) = o;
}

__global__ void __launch_bounds__(256)
k_agg64(const __half* __restrict__ h, const int* __restrict__ off,
        const int* __restrict__ csr, const float* __restrict__ dinv,
        const float* __restrict__ bias, float* __restrict__ out, int Nn) {
    int gt = blockIdx.x * blockDim.x + threadIdx.x;
    int node = gt >> 4;
    int lane = gt & 15;
    if (node >= Nn) return;
    int i  = __ldg(off + node);
    int s1 = __ldg(off + node + 1);

    float4 acc = make_float4(0.f, 0.f, 0.f, 0.f);
#pragma unroll 1
    for (; i + 4 <= s1; i += 4) {
        int sa = __ldg(csr + i);
        int sb = __ldg(csr + i + 1);
        int sc = __ldg(csr + i + 2);
        int sd = __ldg(csr + i + 3);
        __half2 a0 = __ldg((const __half2*)(h + (size_t)sa * 64) + lane * 2);
        __half2 a1 = __ldg((const __half2*)(h + (size_t)sa * 64) + lane * 2 + 1);
        __half2 b0 = __ldg((const __half2*)(h + (size_t)sb * 64) + lane * 2);
        __half2 b1 = __ldg((const __half2*)(h + (size_t)sb * 64) + lane * 2 + 1);
        __half2 c0 = __ldg((const __half2*)(h + (size_t)sc * 64) + lane * 2);
        __half2 c1 = __ldg((const __half2*)(h + (size_t)sc * 64) + lane * 2 + 1);
        __half2 d0 = __ldg((const __half2*)(h + (size_t)sd * 64) + lane * 2);
        __half2 d1 = __ldg((const __half2*)(h + (size_t)sd * 64) + lane * 2 + 1);
        float2 fa0 = __half22float2(a0), fa1 = __half22float2(a1);
        float2 fb0 = __half22float2(b0), fb1 = __half22float2(b1);
        float2 fc0 = __half22float2(c0), fc1 = __half22float2(c1);
        float2 fd0 = __half22float2(d0), fd1 = __half22float2(d1);
        acc.x += (fa0.x + fb0.x) + (fc0.x + fd0.x);
        acc.y += (fa0.y + fb0.y) + (fc0.y + fd0.y);
        acc.z += (fa1.x + fb1.x) + (fc1.x + fd1.x);
        acc.w += (fa1.y + fb1.y) + (fc1.y + fd1.y);
    }
    for (; i < s1; i++) {
        int s = __ldg(csr + i);
        __half2 v0 = __ldg((const __half2*)(h + (size_t)s * 64) + lane * 2);
        __half2 v1 = __ldg((const __half2*)(h + (size_t)s * 64) + lane * 2 + 1);
        float2 f0 = __half22float2(v0), f1 = __half22float2(v1);
        acc.x += f0.x; acc.y += f0.y; acc.z += f1.x; acc.w += f1.y;
    }
    float dv = __ldg(dinv + node);
    float4 bv = __ldg((const float4*)bias + lane);
    float4 o = make_float4(acc.x * dv + bv.x, acc.y * dv + bv.y,
                           acc.z * dv + bv.z, acc.w * dv + bv.w);
    *(float4*)(out + (size_t)node * 64 + lane * 4) = o;
}

// ---------------------------------------------------------------------------
extern "C" void kernel_launch(void* const* d_in, const int* in_sizes, int n_in,
                              void* d_out, int out_size) {
    const float* x  = (const float*)d_in[0];
    const int*   ei = (const int*)  d_in[1];
    const float* W1 = (const float*)d_in[2];
    const float* b1 = (const float*)d_in[3];
    const float* W2 = (const float*)d_in[4];
    const float* b2 = (const float*)d_in[5];
    const float* W3 = (const float*)d_in[6];
    const float* b3 = (const float*)d_in[7];

    const int E = in_sizes[1] / 2;
    const int M = in_sizes[0] / 128;
    const int* src = ei;
    const int* dst = ei + E;

    __half* h;
    float *agg, *dinv;
    int *deg, *off, *cur, *csr, *bsum;
    cudaGetSymbolAddress((void**)&h,    g_h);
    cudaGetSymbolAddress((void**)&agg,  g_agg);
    cudaGetSymbolAddress((void**)&deg,  g_deg);
    cudaGetSymbolAddress((void**)&dinv, g_dinv);
    cudaGetSymbolAddress((void**)&off,  g_off);
    cudaGetSymbolAddress((void**)&cur,  g_cur);
    cudaGetSymbolAddress((void**)&csr,  g_csr);
    cudaGetSymbolAddress((void**)&bsum, g_bsum);
    float* out = (float*)d_out;

    const int nb = (M + SCAN_BLK - 1) / SCAN_BLK;
    const int smem128 = (128 + 128) * APITCH * 2;   // 69632 B
    const int smem64  = (128 + 64)  * APITCH * 2;   // 52224 B
    cudaFuncSetAttribute(k_gemm_hmma<128>, cudaFuncAttributeMaxDynamicSharedMemorySize, smem128);
    cudaFuncSetAttribute(k_gemm_hmma<64>,  cudaFuncAttributeMaxDynamicSharedMemorySize, smem64);

    // --- CSR build + dinv ---
    k_zero_deg<<<(M + 255) / 256, 256>>>(deg, M);
    k_count   <<<(E + 255) / 256, 256>>>(deg, dst, E);
    k_dinv    <<<(M + 255) / 256, 256>>>(dinv, deg, M);
    k_scan1   <<<nb, SCAN_BLK>>>(deg, off, bsum, M);
    k_scan2   <<<1, 32>>>(bsum, nb);
    k_scan3   <<<(M + 255) / 256, 256>>>(off, cur, bsum, M, E);
    k_place   <<<(E + 255) / 256, 256>>>(src, dst, cur, csr, E);

    const int gtiles = (M + 127) / 128;

    // --- layer 1 ---
    k_gemm_hmma<128><<<gtiles, 256, smem128>>>(x, W1, h, dinv, M, 0);
    k_agg128<<<(M * 32 + 255) / 256, 256>>>(h, off, csr, dinv, b1, agg, M);

    // --- layer 2 ---
    k_gemm_hmma<128><<<gtiles, 256, smem128>>>(agg, W2, h, dinv, M, 1);
    k_agg128<<<(M * 32 + 255) / 256, 256>>>(h, off, csr, dinv, b2, agg, M);

    // --- layer 3 (N=64) ---
    k_gemm_hmma<64><<<gtiles, 128, smem64>>>(agg, W3, h, dinv, M, 1);
    k_agg64<<<(M * 16 + 255) / 256, 256>>>(h, off, csr, dinv, b3, out, M);
}

// round 7
// speedup vs baseline: 3.8396x; 1.6696x over previous
#include <cuda_runtime.h>
#include <cuda_fp16.h>
#include <cstdint>
#include <cstddef>

// ---------------------------------------------------------------------------
// GCN, fp16-native dataflow:
//   xh = fp16(x); Wt = fp16(W^T)  (once per replay, cheap)
//   layer: C = fp16( dinv .* (relu(A) @ W) )   [HMMA, cp.async fp16 operands]
//          Anext = fp16( dinv .* csr_sum(C) + b )   [final layer -> fp32 out]
// relu folded into A-fragments (hmax2) -- exact: fp16 rounding commutes w/ relu.
// ---------------------------------------------------------------------------

#define MAX_NODES 100000
#define PAD_ROWS  100096           // 782 tiles * 128
#define MAX_EDGES 1600000
#define SCAN_BLK  1024
#define APITCH    136              // halves per smem row (272B = 17*16B)

__device__ __half g_h [(size_t)PAD_ROWS * 128];   // GEMM output / gather src
__device__ __half g_a [(size_t)PAD_ROWS * 128];   // agg output / GEMM input
__device__ __half g_wt[3 * 128 * 128];            // fp16 W^T: [n][k]
__device__ int    g_deg [MAX_NODES];
__device__ float  g_dinv[MAX_NODES];
__device__ int    g_off [MAX_NODES + 1];
__device__ int    g_cur [MAX_NODES];
__device__ int    g_csr [MAX_EDGES];
__device__ int    g_bsum[(MAX_NODES + SCAN_BLK - 1) / SCAN_BLK];

// ======================= CSR build =========================================
__global__ void k_zero_deg(int* deg, int n) {
    int i = blockIdx.x * blockDim.x + threadIdx.x;
    if (i < n) deg[i] = 0;
}
__global__ void k_count(int* deg, const int* __restrict__ dst, int E) {
    int e = blockIdx.x * blockDim.x + threadIdx.x;
    if (e < E) atomicAdd(&deg[dst[e]], 1);
}
// scan1 also emits dinv (fused)
__global__ void __launch_bounds__(SCAN_BLK)
k_scan1(const int* __restrict__ deg, int* __restrict__ off, int* __restrict__ bsum,
        float* __restrict__ dinv, int n) {
    __shared__ int sh[SCAN_BLK];
    int i = blockIdx.x * SCAN_BLK + threadIdx.x;
    int x = (i < n) ? deg[i] : 0;
    if (i < n) dinv[i] = (x > 0) ? rsqrtf((float)x) : 0.0f;
    sh[threadIdx.x] = x;
    __syncthreads();
#pragma unroll
    for (int s = 1; s < SCAN_BLK; s <<= 1) {
        int v = (threadIdx.x >= s) ? sh[threadIdx.x - s] : 0;
        __syncthreads();
        sh[threadIdx.x] += v;
        __syncthreads();
    }
    if (i < n) off[i] = sh[threadIdx.x] - x;
    if (threadIdx.x == SCAN_BLK - 1) bsum[blockIdx.x] = sh[threadIdx.x];
}
__global__ void k_scan2(int* bsum, int nb) {
    if (threadIdx.x == 0) {
        int run = 0;
        for (int b = 0; b < nb; b++) { int v = bsum[b]; bsum[b] = run; run += v; }
    }
}
__global__ void k_scan3(int* __restrict__ off, int* __restrict__ cur,
                        const int* __restrict__ bsum, int n, int E) {
    int i = blockIdx.x * blockDim.x + threadIdx.x;
    if (i < n) {
        int v = off[i] + bsum[i / SCAN_BLK];
        off[i] = v; cur[i] = v;
    }
    if (i == 0) off[n] = E;
}
__global__ void k_place(const int* __restrict__ src, const int* __restrict__ dst,
                        int* cur, int* __restrict__ csr, int E) {
    int e = blockIdx.x * blockDim.x + threadIdx.x;
    if (e < E) {
        int slot = atomicAdd(&cur[dst[e]], 1);
        csr[slot] = src[e];
    }
}

// ======================= prep: fp16 conversions ============================
__global__ void k_cvt_x(const float* __restrict__ x, __half* __restrict__ xh, int n4) {
    int i = blockIdx.x * blockDim.x + threadIdx.x;
    if (i < n4) {
        float4 v = __ldg((const float4*)x + i);
        __half2* p = (__half2*)(xh + (size_t)i * 4);
        p[0] = __floats2half2_rn(v.x, v.y);
        p[1] = __floats2half2_rn(v.z, v.w);
    }
}
// transpose+convert W1[128x128], W2[128x128], W3[128x64] -> Wt [n][k] fp16
__global__ void k_wt(const float* __restrict__ W1, const float* __restrict__ W2,
                     const float* __restrict__ W3, __half* __restrict__ wt) {
    int i = blockIdx.x * blockDim.x + threadIdx.x;
    if (i < 16384) {                       // W1
        int k = i >> 7, n = i & 127;
        wt[n * 128 + k] = __float2half_rn(__ldg(W1 + k * 128 + n));
    } else if (i < 32768) {                // W2
        int j = i - 16384, k = j >> 7, n = j & 127;
        wt[16384 + n * 128 + k] = __float2half_rn(__ldg(W2 + k * 128 + n));
    } else if (i < 40960) {                // W3: [128][64]
        int j = i - 32768, k = j >> 6, n = j & 63;
        wt[32768 + n * 128 + k] = __float2half_rn(__ldg(W3 + k * 64 + n));
    }
}

// ======================= HMMA GEMM (fp16 in/out, cp.async) =================
__device__ __forceinline__ void ldmx4(uint32_t* r, uint32_t addr) {
    asm volatile("ldmatrix.sync.aligned.m8n8.x4.shared.b16 {%0,%1,%2,%3}, [%4];"
                 : "=r"(r[0]), "=r"(r[1]), "=r"(r[2]), "=r"(r[3]) : "r"(addr));
}
__device__ __forceinline__ void ldmx2(uint32_t* r, uint32_t addr) {
    asm volatile("ldmatrix.sync.aligned.m8n8.x2.shared.b16 {%0,%1}, [%2];"
                 : "=r"(r[0]), "=r"(r[1]) : "r"(addr));
}
__device__ __forceinline__ void mma16816(float* c, const uint32_t* a, const uint32_t* b) {
    asm volatile("mma.sync.aligned.m16n8k16.row.col.f32.f16.f16.f32 "
                 "{%0,%1,%2,%3}, {%4,%5,%6,%7}, {%8,%9}, {%0,%1,%2,%3};"
                 : "+f"(c[0]), "+f"(c[1]), "+f"(c[2]), "+f"(c[3])
                 : "r"(a[0]), "r"(a[1]), "r"(a[2]), "r"(a[3]), "r"(b[0]), "r"(b[1]));
}
__device__ __forceinline__ void cpa16(uint32_t smem, const void* gmem) {
    asm volatile("cp.async.cg.shared.global [%0], [%1], 16;" :: "r"(smem), "l"(gmem));
}

template <int BN>
__global__ void __launch_bounds__(BN * 2)
k_gemm(const __half* __restrict__ A, const __half* __restrict__ Wt,
       __half* __restrict__ C, const float* __restrict__ dinv,
       int M, int relu_in) {
    constexpr int NT  = BN * 2;
    constexpr int NWN = BN / 32;

    extern __shared__ __half sm[];
    __half* As  = sm;                    // [128][APITCH]
    __half* Wts = sm + 128 * APITCH;     // [BN][APITCH]

    const int tid  = threadIdx.x;
    const int wid  = tid >> 5;
    const int lane = tid & 31;
    const int wm   = wid / NWN;
    const int wn   = wid % NWN;
    const int brow = blockIdx.x * 128;

    const uint32_t asb = (uint32_t)__cvta_generic_to_shared(As);
    const uint32_t wsb = (uint32_t)__cvta_generic_to_shared(Wts);

    // ---- cp.async: A tile 128x128 halves (16B chunks), W tile BNx128 ----
#pragma unroll
    for (int idx = tid; idx < 128 * 16; idx += NT) {
        int row = idx >> 4, ch = idx & 15;
        cpa16(asb + (uint32_t)(row * APITCH + ch * 8) * 2,
              A + ((size_t)(brow + row) * 128 + ch * 8));
    }
#pragma unroll
    for (int idx = tid; idx < BN * 16; idx += NT) {
        int n = idx >> 4, ch = idx & 15;
        cpa16(wsb + (uint32_t)(n * APITCH + ch * 8) * 2,
              Wt + ((size_t)n * 128 + ch * 8));
    }
    asm volatile("cp.async.commit_group;");
    asm volatile("cp.async.wait_group 0;" ::: "memory");
    __syncthreads();

    float acc[4][4][4];
#pragma unroll
    for (int i = 0; i < 4; i++)
#pragma unroll
        for (int j = 0; j < 4; j++)
#pragma unroll
            for (int q = 0; q < 4; q++) acc[i][j][q] = 0.0f;

    const int aRow0 = wm * 64 + (lane & 15);
    const int aKoff = (lane >> 4) * 8;
    const int bRow0 = wn * 32 + (lane & 7);
    const int bKoff = ((lane >> 3) & 1) * 8;
    const __half2 z2 = __floats2half2_rn(0.f, 0.f);

#pragma unroll
    for (int ks = 0; ks < 8; ks++) {
        uint32_t a[4][4], b[4][2];
#pragma unroll
        for (int mf = 0; mf < 4; mf++)
            ldmx4(a[mf], asb + (uint32_t)(((aRow0 + mf * 16) * APITCH) + ks * 16 + aKoff) * 2);
        if (relu_in) {
#pragma unroll
            for (int mf = 0; mf < 4; mf++)
#pragma unroll
                for (int q = 0; q < 4; q++) {
                    __half2 v = *(__half2*)&a[mf][q];
                    v = __hmax2(v, z2);
                    a[mf][q] = *(uint32_t*)&v;
                }
        }
#pragma unroll
        for (int nf = 0; nf < 4; nf++)
            ldmx2(b[nf], wsb + (uint32_t)(((bRow0 + nf * 8) * APITCH) + ks * 16 + bKoff) * 2);
#pragma unroll
        for (int mf = 0; mf < 4; mf++)
#pragma unroll
            for (int nf = 0; nf < 4; nf++)
                mma16816(acc[mf][nf], a[mf], b[nf]);
    }

    // ---- epilogue: dinv scale, fp16 store ----
    const int rbase = brow + wm * 64 + (lane >> 2);
    const int cbase = wn * 32 + (lane & 3) * 2;
#pragma unroll
    for (int mf = 0; mf < 4; mf++) {
        int r0 = rbase + mf * 16;
        int r1 = r0 + 8;
        float s0 = (r0 < M) ? __ldg(dinv + r0) : 0.0f;
        float s1 = (r1 < M) ? __ldg(dinv + r1) : 0.0f;
#pragma unroll
        for (int nf = 0; nf < 4; nf++) {
            int col = cbase + nf * 8;
            if (r0 < M)
                *(__half2*)(C + (size_t)r0 * BN + col) =
                    __floats2half2_rn(acc[mf][nf][0] * s0, acc[mf][nf][1] * s0);
            if (r1 < M)
                *(__half2*)(C + (size_t)r1 * BN + col) =
                    __floats2half2_rn(acc[mf][nf][2] * s1, acc[mf][nf][3] * s1);
        }
    }
}

// ===================== CSR gather-sum ======================================
// C=128: warp/node, one 8B uint2 load per edge-lane (256B row), 8x unroll.
__global__ void __launch_bounds__(256)
k_agg128(const __half* __restrict__ h, const int* __restrict__ off,
         const int* __restrict__ csr, const float* __restrict__ dinv,
         const float* __restrict__ bias, __half* __restrict__ out, int Nn) {
    int gt = blockIdx.x * blockDim.x + threadIdx.x;
    int node = gt >> 5;
    int lane = gt & 31;
    if (node >= Nn) return;
    int i  = __ldg(off + node);
    int s1 = __ldg(off + node + 1);
    const uint2* hp = (const uint2*)h;   // row stride = 32 uint2

    float4 acc = make_float4(0.f, 0.f, 0.f, 0.f);
#pragma unroll 1
    for (; i + 8 <= s1; i += 8) {
        int s[8];
#pragma unroll
        for (int j = 0; j < 8; j++) s[j] = __ldg(csr + i + j);
        uint2 v[8];
#pragma unroll
        for (int j = 0; j < 8; j++) v[j] = __ldg(hp + (size_t)s[j] * 32 + lane);
#pragma unroll
        for (int j = 0; j < 8; j++) {
            float2 f0 = __half22float2(*(__half2*)&v[j].x);
            float2 f1 = __half22float2(*(__half2*)&v[j].y);
            acc.x += f0.x; acc.y += f0.y; acc.z += f1.x; acc.w += f1.y;
        }
    }
    for (; i < s1; i++) {
        int s = __ldg(csr + i);
        uint2 v = __ldg(hp + (size_t)s * 32 + lane);
        float2 f0 = __half22float2(*(__half2*)&v.x);
        float2 f1 = __half22float2(*(__half2*)&v.y);
        acc.x += f0.x; acc.y += f0.y; acc.z += f1.x; acc.w += f1.y;
    }
    float dv = __ldg(dinv + node);
    float4 bv = __ldg((const float4*)bias + lane);
    __half2 o0 = __floats2half2_rn(acc.x * dv + bv.x, acc.y * dv + bv.y);
    __half2 o1 = __floats2half2_rn(acc.z * dv + bv.z, acc.w * dv + bv.w);
    uint2 ov;
    ov.x = *(uint32_t*)&o0; ov.y = *(uint32_t*)&o1;
    *((uint2*)out + (size_t)node * 32 + lane) = ov;
}

// C=64 (final): 16 lanes/node, fp32 output.
__global__ void __launch_bounds__(256)
k_agg64(const __half* __restrict__ h, const int* __restrict__ off,
        const int* __restrict__ csr, const float* __restrict__ dinv,
        const float* __restrict__ bias, float* __restrict__ out, int Nn) {
    int gt = blockIdx.x * blockDim.x + threadIdx.x;
    int node = gt >> 4;
    int lane = gt & 15;
    if (node >= Nn) return;
    int i  = __ldg(off + node);
    int s1 = __ldg(off + node + 1);
    const uint2* hp = (const uint2*)h;   // row stride = 16 uint2

    float4 acc = make_float4(0.f, 0.f, 0.f, 0.f);
#pragma unroll 1
    for (; i + 8 <= s1; i += 8) {
        int s[8];
#pragma unroll
        for (int j = 0; j < 8; j++) s[j] = __ldg(csr + i + j);
        uint2 v[8];
#pragma unroll
        for (int j = 0; j < 8; j++) v[j] = __ldg(hp + (size_t)s[j] * 16 + lane);
#pragma unroll
        for (int j = 0; j < 8; j++) {
            float2 f0 = __half22float2(*(__half2*)&v[j].x);
            float2 f1 = __half22float2(*(__half2*)&v[j].y);
            acc.x += f0.x; acc.y += f0.y; acc.z += f1.x; acc.w += f1.y;
        }
    }
    for (; i < s1; i++) {
        int s = __ldg(csr + i);
        uint2 v = __ldg(hp + (size_t)s * 16 + lane);
        float2 f0 = __half22float2(*(__half2*)&v.x);
        float2 f1 = __half22float2(*(__half2*)&v.y);
        acc.x += f0.x; acc.y += f0.y; acc.z += f1.x; acc.w += f1.y;
    }
    float dv = __ldg(dinv + node);
    float4 bv = __ldg((const float4*)bias + lane);
    float4 o = make_float4(acc.x * dv + bv.x, acc.y * dv + bv.y,
                           acc.z * dv + bv.z, acc.w * dv + bv.w);
    *(float4*)(out + (size_t)node * 64 + lane * 4) = o;
}

// ---------------------------------------------------------------------------
extern "C" void kernel_launch(void* const* d_in, const int* in_sizes, int n_in,
                              void* d_out, int out_size) {
    const float* x  = (const float*)d_in[0];
    const int*   ei = (const int*)  d_in[1];
    const float* W1 = (const float*)d_in[2];
    const float* b1 = (const float*)d_in[3];
    const float* W2 = (const float*)d_in[4];
    const float* b2 = (const float*)d_in[5];
    const float* W3 = (const float*)d_in[6];
    const float* b3 = (const float*)d_in[7];

    const int E = in_sizes[1] / 2;
    const int M = in_sizes[0] / 128;
    const int* src = ei;
    const int* dst = ei + E;

    __half *h, *a, *wt;
    float* dinv;
    int *deg, *off, *cur, *csr, *bsum;
    cudaGetSymbolAddress((void**)&h,    g_h);
    cudaGetSymbolAddress((void**)&a,    g_a);
    cudaGetSymbolAddress((void**)&wt,   g_wt);
    cudaGetSymbolAddress((void**)&deg,  g_deg);
    cudaGetSymbolAddress((void**)&dinv, g_dinv);
    cudaGetSymbolAddress((void**)&off,  g_off);
    cudaGetSymbolAddress((void**)&cur,  g_cur);
    cudaGetSymbolAddress((void**)&csr,  g_csr);
    cudaGetSymbolAddress((void**)&bsum, g_bsum);
    float* out = (float*)d_out;

    const int nb = (M + SCAN_BLK - 1) / SCAN_BLK;
    const int smem128 = (128 + 128) * APITCH * 2;   // 69632
    const int smem64  = (128 + 64)  * APITCH * 2;   // 52224
    cudaFuncSetAttribute(k_gemm<128>, cudaFuncAttributeMaxDynamicSharedMemorySize, smem128);
    cudaFuncSetAttribute(k_gemm<64>,  cudaFuncAttributeMaxDynamicSharedMemorySize, smem64);

    // --- CSR build + prep (independent of each other until gemm1/agg1) ---
    k_zero_deg<<<(M + 255) / 256, 256>>>(deg, M);
    k_count   <<<(E + 255) / 256, 256>>>(deg, dst, E);
    k_scan1   <<<nb, SCAN_BLK>>>(deg, off, bsum, dinv, M);
    k_scan2   <<<1, 32>>>(bsum, nb);
    k_scan3   <<<(M + 255) / 256, 256>>>(off, cur, bsum, M, E);
    k_place   <<<(E + 255) / 256, 256>>>(src, dst, cur, csr, E);
    k_cvt_x   <<<(M * 32 + 255) / 256, 256>>>(x, a, M * 32);
    k_wt      <<<(40960 + 255) / 256, 256>>>(W1, W2, W3, wt);

    const int gtiles = (M + 127) / 128;

    // --- layer 1 ---
    k_gemm<128><<<gtiles, 256, smem128>>>(a, wt,          h, dinv, M, 0);
    k_agg128<<<(M * 32 + 255) / 256, 256>>>(h, off, csr, dinv, b1, a, M);

    // --- layer 2 ---
    k_gemm<128><<<gtiles, 256, smem128>>>(a, wt + 16384,  h, dinv, M, 1);
    k_agg128<<<(M * 32 + 255) / 256, 256>>>(h, off, csr, dinv, b2, a, M);

    // --- layer 3 (N=64) ---
    k_gemm<64><<<gtiles, 128, smem64>>>(a, wt + 32768,    h, dinv, M, 1);
    k_agg64<<<(M * 16 + 255) / 256, 256>>>(h, off, csr, dinv, b3, out, M);
}